// round 2
// baseline (speedup 1.0000x reference)
#include <cuda_runtime.h>

// Problem constants (fixed by the reference)
#define NNODES 100000
#define DEG    16
#define FDIM   128
#define HDIM   128
#define ODIM   128
#define BATCH  8192

// Scratch in __device__ globals (no cudaMalloc allowed)
__device__ float g_agg1[(size_t)NNODES * FDIM];   // 51.2 MB
__device__ float g_h1  [(size_t)NNODES * HDIM];   // 51.2 MB
__device__ float g_agg2[(size_t)BATCH  * HDIM];   //  4.2 MB

// ---------------------------------------------------------------------------
// Aggregation: out[i,:] = mean_j src[nbr[map(i)*DEG + j], :]   (rows of 128 f32)
// One warp per output row; each lane owns one float4 (32 lanes * 4 = 128 cols).
// nodes == nullptr -> map(i) = i  (layer 1); else map(i) = nodes[i] (layer 2).
// ---------------------------------------------------------------------------
__global__ __launch_bounds__(256) void agg_kernel(
    const float4* __restrict__ src,
    const int*    __restrict__ nbr,
    const int*    __restrict__ nodes,
    float4*       __restrict__ out,
    int nrows)
{
    int warp = (blockIdx.x * blockDim.x + threadIdx.x) >> 5;
    int lane = threadIdx.x & 31;
    if (warp >= nrows) return;

    int node = nodes ? nodes[warp] : warp;
    const int* nb = nbr + (long long)node * DEG;

    float4 acc = make_float4(0.f, 0.f, 0.f, 0.f);
#pragma unroll
    for (int j = 0; j < DEG; j++) {
        int idx = nb[j];
        float4 v = src[(long long)idx * 32 + lane];
        acc.x += v.x; acc.y += v.y; acc.z += v.z; acc.w += v.w;
    }
    const float s = 1.0f / (float)DEG;
    acc.x *= s; acc.y *= s; acc.z *= s; acc.w *= s;
    out[(long long)warp * 32 + lane] = acc;
}

// ---------------------------------------------------------------------------
// GEMM: C[M,128] = [A0 | A1] @ W,  K = 256, W is [256,128] row-major.
// A0 row m comes from A0 + rowmap(m)*128 (rowmap=nullptr -> identity),
// A1 row m comes from A1 + m*128 (direct).
// Tiling: BM=128, BN=128, BK=32; 256 threads; 8x8 accumulators per thread.
// ---------------------------------------------------------------------------
#define BM 128
#define BN 128
#define BK 32

__global__ __launch_bounds__(256) void gemm_kernel(
    const float* __restrict__ A0,
    const float* __restrict__ A1,
    const int*   __restrict__ rowmap,
    const float* __restrict__ W,
    float*       __restrict__ C,
    int M)
{
    __shared__ float As[BK][BM];   // k-major (transposed) for broadcast reads
    __shared__ float Bs[BK][BN];

    const int tid = threadIdx.x;
    const int block_row = blockIdx.x * BM;
    const int tx = tid & 15;   // 16 col-groups of 8
    const int ty = tid >> 4;   // 16 row-groups of 8

    float acc[8][8];
#pragma unroll
    for (int i = 0; i < 8; i++)
#pragma unroll
        for (int j = 0; j < 8; j++) acc[i][j] = 0.f;

    for (int k0 = 0; k0 < 2 * FDIM; k0 += BK) {
        // --- load W tile: Bs[kk][n], 32x128 f32 = 1024 float4, 4 per thread
#pragma unroll
        for (int i = 0; i < 4; i++) {
            int lin = tid + i * 256;          // 0..1023
            int kk  = lin >> 5;               // 0..31
            int nv  = lin & 31;               // float4 column
            float4 w = reinterpret_cast<const float4*>(W + (long long)(k0 + kk) * 128)[nv];
            *reinterpret_cast<float4*>(&Bs[kk][nv * 4]) = w;
        }
        // --- load A tile (transposed into As[k][m]): 128 rows x 8 float4
#pragma unroll
        for (int i = 0; i < 4; i++) {
            int lin = tid + i * 256;          // 0..1023
            int r   = lin >> 3;               // 0..127
            int kv  = lin & 7;                // float4 within k-chunk
            int grow = block_row + r;
            float4 a = make_float4(0.f, 0.f, 0.f, 0.f);
            int kk = k0 + kv * 4;             // global k (tile never straddles 128)
            if (grow < M) {
                if (kk < FDIM) {
                    int src_row = rowmap ? rowmap[grow] : grow;
                    a = *reinterpret_cast<const float4*>(A0 + (long long)src_row * FDIM + kk);
                } else {
                    a = *reinterpret_cast<const float4*>(A1 + (long long)grow * HDIM + (kk - FDIM));
                }
            }
            int ks = kv * 4;
            As[ks + 0][r] = a.x;
            As[ks + 1][r] = a.y;
            As[ks + 2][r] = a.z;
            As[ks + 3][r] = a.w;
        }
        __syncthreads();

#pragma unroll
        for (int k = 0; k < BK; k++) {
            float a[8], b[8];
#pragma unroll
            for (int i = 0; i < 8; i++) a[i] = As[k][ty * 8 + i];
#pragma unroll
            for (int i = 0; i < 8; i++) b[i] = Bs[k][tx * 8 + i];
#pragma unroll
            for (int i = 0; i < 8; i++)
#pragma unroll
                for (int j = 0; j < 8; j++)
                    acc[i][j] += a[i] * b[j];
        }
        __syncthreads();
    }

    // --- epilogue
#pragma unroll
    for (int i = 0; i < 8; i++) {
        int grow = block_row + ty * 8 + i;
        if (grow < M) {
#pragma unroll
            for (int j = 0; j < 8; j += 4) {
                float4 v = make_float4(acc[i][j], acc[i][j + 1], acc[i][j + 2], acc[i][j + 3]);
                *reinterpret_cast<float4*>(C + (long long)grow * ODIM + tx * 8 + j) = v;
            }
        }
    }
}

// ---------------------------------------------------------------------------
// kernel_launch
// inputs: 0=features[N,128] f32, 1=w1[256,128] f32, 2=w2[256,128] f32,
//         3=neighbor_idx[N,16] i32, 4=nodes[B] i32 ; out = [B,128] f32
// ---------------------------------------------------------------------------
extern "C" void kernel_launch(void* const* d_in, const int* in_sizes, int n_in,
                              void* d_out, int out_size)
{
    const float* features = (const float*)d_in[0];
    const float* w1       = (const float*)d_in[1];
    const float* w2       = (const float*)d_in[2];
    const int*   nbr      = (const int*)  d_in[3];
    const int*   nodes    = (const int*)  d_in[4];
    float*       out      = (float*)d_out;

    const int N = in_sizes[0] / FDIM;   // 100000
    const int Bn = in_sizes[4];         // 8192

    float* agg1 = nullptr; float* h1 = nullptr; float* agg2 = nullptr;
    cudaGetSymbolAddress((void**)&agg1, g_agg1);
    cudaGetSymbolAddress((void**)&h1,   g_h1);
    cudaGetSymbolAddress((void**)&agg2, g_agg2);

    // 1) agg1 = mean neighbor features  (8 warps/block)
    {
        int blocks = (N + 7) / 8;
        agg_kernel<<<blocks, 256>>>((const float4*)features, nbr, nullptr,
                                    (float4*)agg1, N);
    }
    // 2) h1 = [features | agg1] @ w1
    {
        int blocks = (N + BM - 1) / BM;
        gemm_kernel<<<blocks, 256>>>(features, agg1, nullptr, w1, h1, N);
    }
    // 3) agg2 = mean neighbor h1 over nodes' neighbor lists
    {
        int blocks = (Bn + 7) / 8;
        agg_kernel<<<blocks, 256>>>((const float4*)h1, nbr, nodes,
                                    (float4*)agg2, Bn);
    }
    // 4) out = [h1[nodes] | agg2] @ w2
    {
        int blocks = (Bn + BM - 1) / BM;
        gemm_kernel<<<blocks, 256>>>(h1, agg2, nodes, w2, out, Bn);
    }
}

// round 3
// speedup vs baseline: 1.9526x; 1.9526x over previous
#include <cuda_runtime.h>
#include <cuda_bf16.h>
#include <cstdint>

// Problem constants (fixed by the reference)
#define NNODES 100000
#define DEG    16
#define FDIM   128
#define HDIM   128
#define ODIM   128
#define BATCH  8192

// Scratch in __device__ globals (no cudaMalloc allowed)
__device__ float    g_agg1[(size_t)NNODES * FDIM];   // 51.2 MB
__device__ float    g_h1  [(size_t)NNODES * HDIM];   // 51.2 MB
__device__ float    g_agg2[(size_t)BATCH  * HDIM];   //  4.2 MB
// Pre-split, transposed weights: [n][k-pair] packed bf16x2 (k even in low half)
__device__ uint32_t g_w1t_hi[128 * 128];
__device__ uint32_t g_w1t_lo[128 * 128];
__device__ uint32_t g_w2t_hi[128 * 128];
__device__ uint32_t g_w2t_lo[128 * 128];

// ---------------------------------------------------------------------------
// helpers
// ---------------------------------------------------------------------------
__device__ __forceinline__ uint32_t pack_bf16(float lo, float hi) {
    __nv_bfloat162 h = __floats2bfloat162_rn(lo, hi);   // .x = lo (low 16 bits)
    return *reinterpret_cast<uint32_t*>(&h);
}

__device__ __forceinline__ void split_bf16(float x, float& hf, float& lf) {
    __nv_bfloat16 h = __float2bfloat16_rn(x);
    hf = __bfloat162float(h);
    lf = x - hf;
}

__device__ __forceinline__ void mma_bf16(float c[4],
                                         uint32_t a0, uint32_t a1, uint32_t a2, uint32_t a3,
                                         uint32_t b0, uint32_t b1) {
    asm volatile(
        "mma.sync.aligned.m16n8k16.row.col.f32.bf16.bf16.f32 "
        "{%0,%1,%2,%3}, {%4,%5,%6,%7}, {%8,%9}, {%0,%1,%2,%3};"
        : "+f"(c[0]), "+f"(c[1]), "+f"(c[2]), "+f"(c[3])
        : "r"(a0), "r"(a1), "r"(a2), "r"(a3), "r"(b0), "r"(b1));
}

// ---------------------------------------------------------------------------
// Weight prep: W[256][128] f32 -> Wt_hi/Wt_lo[n][k/2] packed bf16x2
// One thread per (n, kpair). 16384 elems per matrix.
// ---------------------------------------------------------------------------
__global__ __launch_bounds__(256) void prep_w_kernel(
    const float* __restrict__ W, uint32_t* __restrict__ Wt_hi, uint32_t* __restrict__ Wt_lo)
{
    int idx = blockIdx.x * blockDim.x + threadIdx.x;   // 0..16383
    if (idx >= 128 * 128) return;
    int n  = idx >> 7;          // 0..127
    int kp = idx & 127;         // k-pair 0..127
    float x0 = W[(2 * kp + 0) * 128 + n];
    float x1 = W[(2 * kp + 1) * 128 + n];
    float h0, l0, h1, l1;
    split_bf16(x0, h0, l0);
    split_bf16(x1, h1, l1);
    Wt_hi[n * 128 + kp] = pack_bf16(h0, h1);
    Wt_lo[n * 128 + kp] = pack_bf16(l0, l1);
}

// ---------------------------------------------------------------------------
// Aggregation: out[i,:] = mean_j src[nbr[map(i)*DEG + j], :]   (rows of 128 f32)
// One warp per output row; each lane owns one float4.
// ---------------------------------------------------------------------------
__global__ __launch_bounds__(256) void agg_kernel(
    const float4* __restrict__ src,
    const int*    __restrict__ nbr,
    const int*    __restrict__ nodes,
    float4*       __restrict__ out,
    int nrows)
{
    int warp = (blockIdx.x * blockDim.x + threadIdx.x) >> 5;
    int lane = threadIdx.x & 31;
    if (warp >= nrows) return;

    int node = nodes ? nodes[warp] : warp;
    const int* nb = nbr + (long long)node * DEG;

    float4 acc = make_float4(0.f, 0.f, 0.f, 0.f);
#pragma unroll
    for (int j = 0; j < DEG; j++) {
        int idx = nb[j];
        float4 v = src[(long long)idx * 32 + lane];
        acc.x += v.x; acc.y += v.y; acc.z += v.z; acc.w += v.w;
    }
    const float s = 1.0f / (float)DEG;
    acc.x *= s; acc.y *= s; acc.z *= s; acc.w *= s;
    out[(long long)warp * 32 + lane] = acc;
}

// ---------------------------------------------------------------------------
// Tensor-core GEMM: C[M,128] = [A0 | A1] @ W, K=256, bf16 2-term split (3 mma).
// A0 row m: A0 + rowmap(m)*128 (rowmap null -> identity); A1 row m: direct.
// W pre-transposed/split as Wt[n][kpair].
// Block 128x128, BK=32, 8 warps (4 along M x 2 along N), warp tile 32x64.
// ---------------------------------------------------------------------------
#define BM 128
#define BK 32
#define SMS 20   // smem row stride (uint32) for 16 k-pairs: conflict-free

__global__ __launch_bounds__(256) void gemm_tc_kernel(
    const float*    __restrict__ A0,
    const float*    __restrict__ A1,
    const int*      __restrict__ rowmap,
    const uint32_t* __restrict__ Wt_hi,
    const uint32_t* __restrict__ Wt_lo,
    float*          __restrict__ C,
    int M)
{
    __shared__ uint32_t As_hi[BM][SMS];
    __shared__ uint32_t As_lo[BM][SMS];
    __shared__ uint32_t Bs_hi[128][SMS];
    __shared__ uint32_t Bs_lo[128][SMS];

    const int tid  = threadIdx.x;
    const int lane = tid & 31;
    const int warp = tid >> 5;
    const int wm   = warp & 3;    // 4 m-tiles of 32 rows
    const int wn   = warp >> 2;   // 2 n-tiles of 64 cols
    const int g    = lane >> 2;
    const int tig  = lane & 3;
    const int block_row = blockIdx.x * BM;

    float acc[2][8][4];
#pragma unroll
    for (int mi = 0; mi < 2; mi++)
#pragma unroll
        for (int ni = 0; ni < 8; ni++)
#pragma unroll
            for (int j = 0; j < 4; j++) acc[mi][ni][j] = 0.f;

    const int arow  = tid >> 1;          // 0..127 (A smem row this thread fills)
    const int aq0   = (tid & 1) * 4;     // first float4 quad of this thread
    const int brow  = tid >> 1;          // 0..127 (B smem row)
    const int bpart = tid & 1;

    // resolve gathered A0 row pointer once
    int grow = block_row + arow;
    const float* a0row = nullptr;
    const float* a1row = nullptr;
    if (grow < M) {
        int src_row = rowmap ? rowmap[grow] : grow;
        a0row = A0 + (long long)src_row * FDIM;
        a1row = A1 + (long long)grow * HDIM;
    }

    for (int k0 = 0; k0 < 2 * FDIM; k0 += BK) {
        // ---- stage A tile: split f32 -> bf16 hi/lo pairs
        const float* arow_ptr = (k0 < FDIM) ? a0row : a1row;
        int akofs = (k0 < FDIM) ? k0 : (k0 - FDIM);
#pragma unroll
        for (int i = 0; i < 4; i++) {
            int q = aq0 + i;                              // float4 quad 0..7
            float4 v = make_float4(0.f, 0.f, 0.f, 0.f);
            if (arow_ptr)
                v = *reinterpret_cast<const float4*>(arow_ptr + akofs + q * 4);
            float hx, lx, hy, ly, hz, lz, hw, lw;
            split_bf16(v.x, hx, lx); split_bf16(v.y, hy, ly);
            split_bf16(v.z, hz, lz); split_bf16(v.w, hw, lw);
            As_hi[arow][q * 2 + 0] = pack_bf16(hx, hy);
            As_hi[arow][q * 2 + 1] = pack_bf16(hz, hw);
            As_lo[arow][q * 2 + 0] = pack_bf16(lx, ly);
            As_lo[arow][q * 2 + 1] = pack_bf16(lz, lw);
        }
        // ---- stage B tile: copy pre-split weights (uint4, 16B aligned: 20%4==0)
        {
            int kp0 = k0 >> 1;                            // first k-pair of tile
#pragma unroll
            for (int i = 0; i < 2; i++) {
                int q = bpart * 2 + i;                    // uint4 quad 0..3
                uint4 vh = *reinterpret_cast<const uint4*>(Wt_hi + brow * 128 + kp0 + q * 4);
                uint4 vl = *reinterpret_cast<const uint4*>(Wt_lo + brow * 128 + kp0 + q * 4);
                *reinterpret_cast<uint4*>(&Bs_hi[brow][q * 4]) = vh;
                *reinterpret_cast<uint4*>(&Bs_lo[brow][q * 4]) = vl;
            }
        }
        __syncthreads();

        // ---- compute: 2 k16 steps per BK
#pragma unroll
        for (int kk = 0; kk < 2; kk++) {
            const int kb = kk * 8;
            uint32_t ah[2][4], al[2][4];
#pragma unroll
            for (int mi = 0; mi < 2; mi++) {
                int r = wm * 32 + mi * 16 + g;
                ah[mi][0] = As_hi[r][kb + tig];
                ah[mi][1] = As_hi[r + 8][kb + tig];
                ah[mi][2] = As_hi[r][kb + tig + 4];
                ah[mi][3] = As_hi[r + 8][kb + tig + 4];
                al[mi][0] = As_lo[r][kb + tig];
                al[mi][1] = As_lo[r + 8][kb + tig];
                al[mi][2] = As_lo[r][kb + tig + 4];
                al[mi][3] = As_lo[r + 8][kb + tig + 4];
            }
#pragma unroll
            for (int ni = 0; ni < 8; ni++) {
                int c = wn * 64 + ni * 8 + g;
                uint32_t bh0 = Bs_hi[c][kb + tig];
                uint32_t bh1 = Bs_hi[c][kb + tig + 4];
                uint32_t bl0 = Bs_lo[c][kb + tig];
                uint32_t bl1 = Bs_lo[c][kb + tig + 4];
#pragma unroll
                for (int mi = 0; mi < 2; mi++) {
                    mma_bf16(acc[mi][ni], ah[mi][0], ah[mi][1], ah[mi][2], ah[mi][3], bh0, bh1);
                    mma_bf16(acc[mi][ni], ah[mi][0], ah[mi][1], ah[mi][2], ah[mi][3], bl0, bl1);
                    mma_bf16(acc[mi][ni], al[mi][0], al[mi][1], al[mi][2], al[mi][3], bh0, bh1);
                }
            }
        }
        __syncthreads();
    }

    // ---- epilogue: float2 stores
#pragma unroll
    for (int mi = 0; mi < 2; mi++) {
        int r0 = block_row + wm * 32 + mi * 16 + g;
#pragma unroll
        for (int ni = 0; ni < 8; ni++) {
            int col = wn * 64 + ni * 8 + tig * 2;
            if (r0 < M)
                *reinterpret_cast<float2*>(C + (long long)r0 * ODIM + col) =
                    make_float2(acc[mi][ni][0], acc[mi][ni][1]);
            if (r0 + 8 < M)
                *reinterpret_cast<float2*>(C + (long long)(r0 + 8) * ODIM + col) =
                    make_float2(acc[mi][ni][2], acc[mi][ni][3]);
        }
    }
}

// ---------------------------------------------------------------------------
// kernel_launch
// inputs: 0=features[N,128] f32, 1=w1[256,128] f32, 2=w2[256,128] f32,
//         3=neighbor_idx[N,16] i32, 4=nodes[B] i32 ; out = [B,128] f32
// ---------------------------------------------------------------------------
extern "C" void kernel_launch(void* const* d_in, const int* in_sizes, int n_in,
                              void* d_out, int out_size)
{
    const float* features = (const float*)d_in[0];
    const float* w1       = (const float*)d_in[1];
    const float* w2       = (const float*)d_in[2];
    const int*   nbr      = (const int*)  d_in[3];
    const int*   nodes    = (const int*)  d_in[4];
    float*       out      = (float*)d_out;

    const int N  = in_sizes[0] / FDIM;   // 100000
    const int Bn = in_sizes[4];          // 8192

    float *agg1, *h1, *agg2;
    uint32_t *w1t_hi, *w1t_lo, *w2t_hi, *w2t_lo;
    cudaGetSymbolAddress((void**)&agg1,   g_agg1);
    cudaGetSymbolAddress((void**)&h1,     g_h1);
    cudaGetSymbolAddress((void**)&agg2,   g_agg2);
    cudaGetSymbolAddress((void**)&w1t_hi, g_w1t_hi);
    cudaGetSymbolAddress((void**)&w1t_lo, g_w1t_lo);
    cudaGetSymbolAddress((void**)&w2t_hi, g_w2t_hi);
    cudaGetSymbolAddress((void**)&w2t_lo, g_w2t_lo);

    // 0) pre-split/transpose weights
    prep_w_kernel<<<64, 256>>>(w1, w1t_hi, w1t_lo);
    prep_w_kernel<<<64, 256>>>(w2, w2t_hi, w2t_lo);

    // 1) agg1 = mean neighbor features
    agg_kernel<<<(N + 7) / 8, 256>>>((const float4*)features, nbr, nullptr,
                                     (float4*)agg1, N);
    // 2) h1 = [features | agg1] @ w1   (tensor cores)
    gemm_tc_kernel<<<(N + BM - 1) / BM, 256>>>(features, agg1, nullptr,
                                               w1t_hi, w1t_lo, h1, N);
    // 3) agg2 = mean neighbor h1 over the batch nodes
    agg_kernel<<<(Bn + 7) / 8, 256>>>((const float4*)h1, nbr, nodes,
                                      (float4*)agg2, Bn);
    // 4) out = [h1[nodes] | agg2] @ w2   (tensor cores)
    gemm_tc_kernel<<<(Bn + BM - 1) / BM, 256>>>(h1, agg2, nodes,
                                                w2t_hi, w2t_lo, out, Bn);
}

// round 5
// speedup vs baseline: 2.3530x; 1.2050x over previous
#include <cuda_runtime.h>
#include <cuda_bf16.h>
#include <cstdint>

// Problem constants (fixed by the reference)
#define NNODES 100000
#define DEG    16
#define FDIM   128
#define HDIM   128
#define ODIM   128
#define BATCH  8192

// Scratch in __device__ globals (no cudaMalloc allowed)
__device__ float    g_agg1[(size_t)NNODES * FDIM];   // 51.2 MB
__device__ float    g_h1  [(size_t)NNODES * HDIM];   // 51.2 MB
__device__ float    g_agg2[(size_t)BATCH  * HDIM];   //  4.2 MB
// Pre-split, transposed weights: [n][k-pair] packed bf16x2 (k even in low half)
__device__ uint32_t g_w1t_hi[128 * 128];
__device__ uint32_t g_w1t_lo[128 * 128];
__device__ uint32_t g_w2t_hi[128 * 128];
__device__ uint32_t g_w2t_lo[128 * 128];

// ---------------------------------------------------------------------------
// helpers
// ---------------------------------------------------------------------------
__device__ __forceinline__ uint32_t pack_bf16(float lo, float hi) {
    __nv_bfloat162 h = __floats2bfloat162_rn(lo, hi);   // .x = lo (low 16 bits)
    return *reinterpret_cast<uint32_t*>(&h);
}

__device__ __forceinline__ void split_bf16(float x, float& hf, float& lf) {
    __nv_bfloat16 h = __float2bfloat16_rn(x);
    hf = __bfloat162float(h);
    lf = x - hf;
}

__device__ __forceinline__ void mma_bf16(float c[4],
                                         uint32_t a0, uint32_t a1, uint32_t a2, uint32_t a3,
                                         uint32_t b0, uint32_t b1) {
    asm volatile(
        "mma.sync.aligned.m16n8k16.row.col.f32.bf16.bf16.f32 "
        "{%0,%1,%2,%3}, {%4,%5,%6,%7}, {%8,%9}, {%0,%1,%2,%3};"
        : "+f"(c[0]), "+f"(c[1]), "+f"(c[2]), "+f"(c[3])
        : "r"(a0), "r"(a1), "r"(a2), "r"(a3), "r"(b0), "r"(b1));
}

__device__ __forceinline__ void cp_async16(uint32_t smem_addr, const void* gptr) {
    asm volatile("cp.async.ca.shared.global [%0], [%1], 16;\n"
                 :: "r"(smem_addr), "l"(gptr));
}
__device__ __forceinline__ void cp_async_commit() {
    asm volatile("cp.async.commit_group;\n" ::: "memory");
}
__device__ __forceinline__ void cp_async_wait0() {
    asm volatile("cp.async.wait_group 0;\n" ::: "memory");
}

// ---------------------------------------------------------------------------
// Weight prep: W[256][128] f32 -> Wt_hi/Wt_lo[n][k/2] packed bf16x2
// ---------------------------------------------------------------------------
__global__ __launch_bounds__(256) void prep_w_kernel(
    const float* __restrict__ W, uint32_t* __restrict__ Wt_hi, uint32_t* __restrict__ Wt_lo)
{
    int idx = blockIdx.x * blockDim.x + threadIdx.x;   // 0..16383
    if (idx >= 128 * 128) return;
    int n  = idx >> 7;          // 0..127
    int kp = idx & 127;         // k-pair 0..127
    float x0 = W[(2 * kp + 0) * 128 + n];
    float x1 = W[(2 * kp + 1) * 128 + n];
    float h0, l0, h1, l1;
    split_bf16(x0, h0, l0);
    split_bf16(x1, h1, l1);
    Wt_hi[n * 128 + kp] = pack_bf16(h0, h1);
    Wt_lo[n * 128 + kp] = pack_bf16(l0, l1);
}

// ---------------------------------------------------------------------------
// Aggregation: out[i,:] = mean_j src[nbr[map(i)*DEG + j], :]   (rows of 128 f32)
// One warp per output row; each lane owns one float4.
// ---------------------------------------------------------------------------
__global__ __launch_bounds__(256) void agg_kernel(
    const float4* __restrict__ src,
    const int*    __restrict__ nbr,
    const int*    __restrict__ nodes,
    float4*       __restrict__ out,
    int nrows)
{
    int warp = (blockIdx.x * blockDim.x + threadIdx.x) >> 5;
    int lane = threadIdx.x & 31;
    if (warp >= nrows) return;

    int node = nodes ? nodes[warp] : warp;
    const int* nb = nbr + (long long)node * DEG;

    float4 acc = make_float4(0.f, 0.f, 0.f, 0.f);
#pragma unroll
    for (int j = 0; j < DEG; j++) {
        int idx = nb[j];
        float4 v = src[(long long)idx * 32 + lane];
        acc.x += v.x; acc.y += v.y; acc.z += v.z; acc.w += v.w;
    }
    const float s = 1.0f / (float)DEG;
    acc.x *= s; acc.y *= s; acc.z *= s; acc.w *= s;
    out[(long long)warp * 32 + lane] = acc;
}

// ---------------------------------------------------------------------------
// Tensor-core GEMM, software-pipelined with double-buffered smem.
// C[M,128] = [A0 | A1] @ W, K=256, bf16 2-term split (3 mma per k16 step).
// A0 row m: A0 + rowmap(m)*128 (rowmap null -> identity); A1 row m: direct.
// W pre-transposed/split as Wt[n][kpair].
// Block 128x128, BK=32 (8 k-tiles), 8 warps (4 M x 2 N), warp tile 32x64.
// Per tile: next-B via cp.async, next-A via LDG->regs; compute current; then
// convert A regs -> other buffer; one __syncthreads per tile.
// ---------------------------------------------------------------------------
#define BM  128
#define BK  32
#define KT  8            // K tiles (256 / 32)
#define SMS 20           // smem row stride (uint32), conflict-free for frags
#define BUFW (128 * SMS) // words per array per buffer

__global__ __launch_bounds__(256) void gemm_tc_kernel(
    const float*    __restrict__ A0,
    const float*    __restrict__ A1,
    const int*      __restrict__ rowmap,
    const uint32_t* __restrict__ Wt_hi,
    const uint32_t* __restrict__ Wt_lo,
    float*          __restrict__ C,
    int M)
{
    extern __shared__ uint32_t smem[];
    uint32_t* as_hi = smem;               // [2][128][SMS]
    uint32_t* as_lo = smem + 2 * BUFW;
    uint32_t* bs_hi = smem + 4 * BUFW;
    uint32_t* bs_lo = smem + 6 * BUFW;
#define ASH(b,r,c) as_hi[(b) * BUFW + (r) * SMS + (c)]
#define ASL(b,r,c) as_lo[(b) * BUFW + (r) * SMS + (c)]
#define BSH(b,r,c) bs_hi[(b) * BUFW + (r) * SMS + (c)]
#define BSL(b,r,c) bs_lo[(b) * BUFW + (r) * SMS + (c)]

    const int tid  = threadIdx.x;
    const int lane = tid & 31;
    const int warp = tid >> 5;
    const int wm   = warp & 3;    // 4 m-tiles of 32 rows
    const int wn   = warp >> 2;   // 2 n-tiles of 64 cols
    const int g    = lane >> 2;
    const int tig  = lane & 3;
    const int block_row = blockIdx.x * BM;

    float acc[2][8][4];
#pragma unroll
    for (int mi = 0; mi < 2; mi++)
#pragma unroll
        for (int ni = 0; ni < 8; ni++)
#pragma unroll
            for (int j = 0; j < 4; j++) acc[mi][ni][j] = 0.f;

    const int arow  = tid >> 1;          // 0..127 (A smem row this thread fills)
    const int aq0   = (tid & 1) * 4;     // first float4 quad of this thread
    const int brow  = tid >> 1;          // 0..127 (B smem row)
    const int bpart = tid & 1;

    // resolve gathered A0 row pointer once
    int grow = block_row + arow;
    const float* a0row = nullptr;
    const float* a1row = nullptr;
    if (grow < M) {
        int src_row = rowmap ? rowmap[grow] : grow;
        a0row = A0 + (long long)src_row * FDIM;
        a1row = A1 + (long long)grow * HDIM;
    }

    // smem byte addresses for this thread's B destinations (per buffer)
    uint32_t bsh_base = (uint32_t)__cvta_generic_to_shared(&BSH(0, brow, 0));
    uint32_t bsl_base = (uint32_t)__cvta_generic_to_shared(&BSL(0, brow, 0));

    // ---- stage helpers (macros to keep everything in registers) ----
    // issue B cp.asyncs for tile t into buffer b
#define STAGE_B(t, b) do {                                                     \
        int kp0 = (t) * (BK / 2);                                              \
        _Pragma("unroll")                                                      \
        for (int i = 0; i < 2; i++) {                                          \
            int q = bpart * 2 + i;                                             \
            cp_async16(bsh_base + (b) * BUFW * 4 + q * 16,                     \
                       Wt_hi + brow * 128 + kp0 + q * 4);                      \
            cp_async16(bsl_base + (b) * BUFW * 4 + q * 16,                     \
                       Wt_lo + brow * 128 + kp0 + q * 4);                      \
        }                                                                      \
    } while (0)

    // load A tile t into regs va[4]
#define LOAD_A(t, va) do {                                                     \
        const float* p = ((t) < 4) ? a0row : a1row;                            \
        int akofs = ((t) & 3) * BK;                                            \
        _Pragma("unroll")                                                      \
        for (int i = 0; i < 4; i++) {                                          \
            int q = aq0 + i;                                                   \
            va[i] = p ? *reinterpret_cast<const float4*>(p + akofs + q * 4)    \
                      : make_float4(0.f, 0.f, 0.f, 0.f);                       \
        }                                                                      \
    } while (0)

    // convert regs -> smem buffer b
#define STORE_A(b, va) do {                                                    \
        _Pragma("unroll")                                                      \
        for (int i = 0; i < 4; i++) {                                          \
            int q = aq0 + i;                                                   \
            float hx, lx, hy, ly, hz, lz, hw, lw;                              \
            split_bf16(va[i].x, hx, lx); split_bf16(va[i].y, hy, ly);          \
            split_bf16(va[i].z, hz, lz); split_bf16(va[i].w, hw, lw);          \
            ASH((b), arow, q * 2 + 0) = pack_bf16(hx, hy);                     \
            ASH((b), arow, q * 2 + 1) = pack_bf16(hz, hw);                     \
            ASL((b), arow, q * 2 + 0) = pack_bf16(lx, ly);                     \
            ASL((b), arow, q * 2 + 1) = pack_bf16(lz, lw);                     \
        }                                                                      \
    } while (0)

    // ---- prologue: tile 0 -> buffer 0
    {
        STAGE_B(0, 0);
        cp_async_commit();
        float4 va[4];
        LOAD_A(0, va);
        STORE_A(0, va);
        cp_async_wait0();
    }

    // ---- main loop
    for (int t = 0; t < KT; t++) {
        __syncthreads();
        const int cb = t & 1;
        const int nb = (t + 1) & 1;
        const bool have_next = (t + 1 < KT);

        float4 va[4];
        if (have_next) {
            STAGE_B(t + 1, nb);
            cp_async_commit();
            LOAD_A(t + 1, va);
        }

        // ---- compute on buffer cb: 2 k16 steps
#pragma unroll
        for (int kk = 0; kk < 2; kk++) {
            const int kb = kk * 8;
            uint32_t ah[2][4], al[2][4];
#pragma unroll
            for (int mi = 0; mi < 2; mi++) {
                int r = wm * 32 + mi * 16 + g;
                ah[mi][0] = ASH(cb, r,     kb + tig);
                ah[mi][1] = ASH(cb, r + 8, kb + tig);
                ah[mi][2] = ASH(cb, r,     kb + tig + 4);
                ah[mi][3] = ASH(cb, r + 8, kb + tig + 4);
                al[mi][0] = ASL(cb, r,     kb + tig);
                al[mi][1] = ASL(cb, r + 8, kb + tig);
                al[mi][2] = ASL(cb, r,     kb + tig + 4);
                al[mi][3] = ASL(cb, r + 8, kb + tig + 4);
            }
#pragma unroll
            for (int ni = 0; ni < 8; ni++) {
                int c = wn * 64 + ni * 8 + g;
                uint32_t bh0 = BSH(cb, c, kb + tig);
                uint32_t bh1 = BSH(cb, c, kb + tig + 4);
                uint32_t bl0 = BSL(cb, c, kb + tig);
                uint32_t bl1 = BSL(cb, c, kb + tig + 4);
#pragma unroll
                for (int mi = 0; mi < 2; mi++) {
                    mma_bf16(acc[mi][ni], ah[mi][0], ah[mi][1], ah[mi][2], ah[mi][3], bh0, bh1);
                    mma_bf16(acc[mi][ni], ah[mi][0], ah[mi][1], ah[mi][2], ah[mi][3], bl0, bl1);
                    mma_bf16(acc[mi][ni], al[mi][0], al[mi][1], al[mi][2], al[mi][3], bh0, bh1);
                }
            }
        }

        if (have_next) {
            STORE_A(nb, va);
            cp_async_wait0();
        }
    }

    // ---- epilogue: float2 stores
#pragma unroll
    for (int mi = 0; mi < 2; mi++) {
        int r0 = block_row + wm * 32 + mi * 16 + g;
#pragma unroll
        for (int ni = 0; ni < 8; ni++) {
            int col = wn * 64 + ni * 8 + tig * 2;
            if (r0 < M)
                *reinterpret_cast<float2*>(C + (long long)r0 * ODIM + col) =
                    make_float2(acc[mi][ni][0], acc[mi][ni][1]);
            if (r0 + 8 < M)
                *reinterpret_cast<float2*>(C + (long long)(r0 + 8) * ODIM + col) =
                    make_float2(acc[mi][ni][2], acc[mi][ni][3]);
        }
    }
}

// ---------------------------------------------------------------------------
// kernel_launch
// inputs: 0=features[N,128] f32, 1=w1[256,128] f32, 2=w2[256,128] f32,
//         3=neighbor_idx[N,16] i32, 4=nodes[B] i32 ; out = [B,128] f32
// ---------------------------------------------------------------------------
extern "C" void kernel_launch(void* const* d_in, const int* in_sizes, int n_in,
                              void* d_out, int out_size)
{
    const float* features = (const float*)d_in[0];
    const float* w1       = (const float*)d_in[1];
    const float* w2       = (const float*)d_in[2];
    const int*   nbr      = (const int*)  d_in[3];
    const int*   nodes    = (const int*)  d_in[4];
    float*       out      = (float*)d_out;

    const int N  = in_sizes[0] / FDIM;   // 100000
    const int Bn = in_sizes[4];          // 8192

    float *agg1, *h1, *agg2;
    uint32_t *w1t_hi, *w1t_lo, *w2t_hi, *w2t_lo;
    cudaGetSymbolAddress((void**)&agg1,   g_agg1);
    cudaGetSymbolAddress((void**)&h1,     g_h1);
    cudaGetSymbolAddress((void**)&agg2,   g_agg2);
    cudaGetSymbolAddress((void**)&w1t_hi, g_w1t_hi);
    cudaGetSymbolAddress((void**)&w1t_lo, g_w1t_lo);
    cudaGetSymbolAddress((void**)&w2t_hi, g_w2t_hi);
    cudaGetSymbolAddress((void**)&w2t_lo, g_w2t_lo);

    const int smem_bytes = 8 * BUFW * 4;   // 81920 B
    static bool attr_set = false;
    if (!attr_set) {
        cudaFuncSetAttribute(gemm_tc_kernel,
                             cudaFuncAttributeMaxDynamicSharedMemorySize, smem_bytes);
        attr_set = true;
    }

    // 0) pre-split/transpose weights
    prep_w_kernel<<<64, 256>>>(w1, w1t_hi, w1t_lo);
    prep_w_kernel<<<64, 256>>>(w2, w2t_hi, w2t_lo);

    // 1) agg1 = mean neighbor features
    agg_kernel<<<(N + 7) / 8, 256>>>((const float4*)features, nbr, nullptr,
                                     (float4*)agg1, N);
    // 2) h1 = [features | agg1] @ w1   (tensor cores, pipelined)
    gemm_tc_kernel<<<(N + BM - 1) / BM, 256, smem_bytes>>>(
        features, agg1, nullptr, w1t_hi, w1t_lo, h1, N);
    // 3) agg2 = mean neighbor h1 over the batch nodes
    agg_kernel<<<(Bn + 7) / 8, 256>>>((const float4*)h1, nbr, nodes,
                                      (float4*)agg2, Bn);
    // 4) out = [h1[nodes] | agg2] @ w2   (tensor cores, pipelined)
    gemm_tc_kernel<<<(Bn + BM - 1) / BM, 256, smem_bytes>>>(
        h1, agg2, nodes, w2t_hi, w2t_lo, out, Bn);
}